// round 10
// baseline (speedup 1.0000x reference)
#include <cuda_runtime.h>
#include <math.h>

#define Bn 4
#define Tn 8192
#define Dn 512
#define Sn 16
#define PARTS 64   // 256 blocks / 4 batches in the fused attn+G pass

// Scratch (static device globals — allocation-free per harness rules)
__device__ float g_attn [Bn*Tn*Sn];          // 2 MB
__device__ float g_Gpart[Bn*PARTS*Sn*Dn];    // 8 MB
__device__ float g_G    [Bn*Sn*Dn];
__device__ float g_H    [Bn*Sn*Dn];
__device__ float g_M    [Bn*Sn*Dn];

__device__ __forceinline__ unsigned f2tf32(float f) {
    unsigned r; asm("cvt.rna.tf32.f32 %0, %1;" : "=r"(r) : "f"(f));
    return r;
}

__device__ __forceinline__ void mma_tf32(float c[4],
    unsigned a0, unsigned a1, unsigned a2, unsigned a3,
    unsigned b0, unsigned b1) {
    asm("mma.sync.aligned.m16n8k8.row.col.f32.tf32.tf32.f32 "
        "{%0,%1,%2,%3}, {%4,%5,%6,%7}, {%8,%9}, {%0,%1,%2,%3};"
        : "+f"(c[0]), "+f"(c[1]), "+f"(c[2]), "+f"(c[3])
        : "r"(a0), "r"(a1), "r"(a2), "r"(a3), "r"(b0), "r"(b1));
}

// 8-lane reduction (lanes differing in bits 0..2)
__device__ __forceinline__ float red8(float v) {
    v += __shfl_xor_sync(0xffffffffu, v, 1);
    v += __shfl_xor_sync(0xffffffffu, v, 2);
    v += __shfl_xor_sync(0xffffffffu, v, 4);
    return v;
}

// Reduce acc[16] with 16 shuffles; result for index (lane>>1)&15 on even lanes.
__device__ __forceinline__ float reduce16_scatter(float* acc, int lane) {
#pragma unroll
    for (int step = 16, n = 8; n >= 1; step >>= 1, n >>= 1) {
        bool hi = (lane & step) != 0;
#pragma unroll
        for (int i = 0; i < n; i++) {
            float send = hi ? acc[i] : acc[i + n];
            float recv = __shfl_xor_sync(0xffffffffu, send, step);
            acc[i] = (hi ? acc[i + n] : acc[i]) + recv;
        }
    }
    float v = acc[0];
    v += __shfl_xor_sync(0xffffffffu, v, 1);
    return v;
}

// ---------------------------------------------------------------------------
// Kernel 1 (fused): attention weights (tf32 MMA for xc; x2 folded into the
// staging loop) + partial G = attn^T x ALSO via tf32 MMA with smem-staged A.
// Grid 256 x 256 thr, 128 tokens/block.
// ---------------------------------------------------------------------------
__global__ __launch_bounds__(256) void k_attn_g(const float* __restrict__ x,
                                                const float* __restrict__ centers,
                                                const float* __restrict__ log_scales) {
    __shared__ float    s_x   [128 * 36];    // tf32 x chunk, padded (18 KB) — reused in both phases
    __shared__ unsigned s_bf  [512];         // B fragments (centers) per chunk (2 KB)
    __shared__ union {                       // xc dead after softmax -> reuse for attn B-frags
        float    xc[128 * 17];               // 8.7 KB
        unsigned bfa[2048];                  // 8 KB
    } s_u2;
    __shared__ union {                       // attn dead after copy/bfa-build -> reuse for k-half combine
        float attn[128 * Sn];                // 8 KB
        float comb[4 * 32 * 4];              // 2 KB
    } s_u3;
    __shared__ float    s_x2  [128];
    __shared__ float    s_part[256];
    __shared__ float    s_inv [Sn], s_bias[Sn];

    int tid  = threadIdx.x;
    int warp = tid >> 5, lane = tid & 31;
    int gid  = lane >> 2, tg = lane & 3;     // mma fragment coords
    long long tok0 = (long long)blockIdx.x * 128;
    const float* xb = x + tok0 * Dn;

    // ---- scale/bias precompute: c2 via 16 threads per splat ----
    {
        int sp = tid >> 4, p16 = tid & 15;
        const float4* cr = (const float4*)(centers + (long long)sp * Dn);
        float c2 = 0.f;
#pragma unroll
        for (int j = 0; j < 8; j++) {
            float4 v = cr[p16 + j * 16];
            c2 += v.x * v.x + v.y * v.y + v.z * v.z + v.w * v.w;
        }
        s_part[tid] = c2;
        __syncthreads();
        if (tid < Sn) {
            float c2t = 0.f;
#pragma unroll
            for (int k = 0; k < 16; k++) c2t += s_part[tid * 16 + k];
            float s = expf(log_scales[tid]);
            s = fminf(fmaxf(s, 0.1f), 2.0f);
            float inv = -0.5f / (s * s);
            s_inv[tid]  = inv;
            s_bias[tid] = inv * c2t;
        }
    }

    // ---- Phase 1: XC = x . centers^T via tf32 mma; x2 folded into staging ----
    float xcacc[2][4];
#pragma unroll
    for (int h = 0; h < 2; h++)
#pragma unroll
        for (int r = 0; r < 4; r++) xcacc[h][r] = 0.f;
    float x2p[4] = {0.f, 0.f, 0.f, 0.f};     // partial x2 for rows (tid>>3)+32i, col tid&7
    int tlw = warp * 16;                     // warp's m-tile token base

#pragma unroll 1
    for (int c = 0; c < 16; c++) {
        // stage x chunk (cols c*32..+31) as tf32, padded stride 36; fold x2
#pragma unroll
        for (int i = 0; i < 4; i++) {
            int row = (tid >> 3) + i * 32, c4 = tid & 7;
            float4 v = ((const float4*)(xb + (long long)row * Dn))[c * 8 + c4];
            x2p[i] += v.x * v.x + v.y * v.y + v.z * v.z + v.w * v.w;
            float4 t;
            t.x = __uint_as_float(f2tf32(v.x));
            t.y = __uint_as_float(f2tf32(v.y));
            t.z = __uint_as_float(f2tf32(v.z));
            t.w = __uint_as_float(f2tf32(v.w));
            *(float4*)&s_x[row * 36 + c4 * 4] = t;
        }
        // B fragments (centers) for this chunk: [kit8][h][which][lane]
#pragma unroll
        for (int i = 0; i < 2; i++) {
            int e = tid + i * 256;           // 0..511
            int kit8 = e >> 7, rem = e & 127;
            int h = rem >> 6, which = (rem >> 5) & 1, L = rem & 31;
            int k  = c * 32 + kit8 * 8 + (L & 3) + which * 4;
            int sp = h * 8 + (L >> 2);
            s_bf[e] = f2tf32(centers[(long long)sp * Dn + k]);
        }
        __syncthreads();
        // 4 k-iterations of m16n8k8 per n-half
#pragma unroll
        for (int kit8 = 0; kit8 < 4; kit8++) {
            int kb = kit8 * 8;
            unsigned a0 = __float_as_uint(s_x[(tlw + gid)     * 36 + kb + tg]);
            unsigned a1 = __float_as_uint(s_x[(tlw + gid + 8) * 36 + kb + tg]);
            unsigned a2 = __float_as_uint(s_x[(tlw + gid)     * 36 + kb + tg + 4]);
            unsigned a3 = __float_as_uint(s_x[(tlw + gid + 8) * 36 + kb + tg + 4]);
#pragma unroll
            for (int h = 0; h < 2; h++) {
                unsigned b0 = s_bf[kit8 * 128 + h * 64 + lane];
                unsigned b1 = s_bf[kit8 * 128 + h * 64 + 32 + lane];
                mma_tf32(xcacc[h], a0, a1, a2, a3, b0, b1);
            }
        }
        __syncthreads();
    }

    // write XC fragments to padded smem
#pragma unroll
    for (int h = 0; h < 2; h++) {
        int col = h * 8 + tg * 2;
        s_u2.xc[(tlw + gid)     * 17 + col]     = xcacc[h][0];
        s_u2.xc[(tlw + gid)     * 17 + col + 1] = xcacc[h][1];
        s_u2.xc[(tlw + gid + 8) * 17 + col]     = xcacc[h][2];
        s_u2.xc[(tlw + gid + 8) * 17 + col + 1] = xcacc[h][3];
    }
    // finish x2: threads sharing a row differ in lane bits 0..2
#pragma unroll
    for (int i = 0; i < 4; i++) {
        float v = red8(x2p[i]);
        if ((tid & 7) == 0) s_x2[(tid >> 3) + i * 32] = v;
    }
    __syncthreads();

    // per-token softmax (threads 0..127)
    if (tid < 128) {
        float x2 = s_x2[tid];
        float l[Sn];
        float m = -1e30f;
#pragma unroll
        for (int s = 0; s < Sn; s++) {
            l[s] = s_inv[s] * (x2 - 2.f * s_u2.xc[tid * 17 + s]) + s_bias[s];
            m = fmaxf(m, l[s]);
        }
        float sum = 0.f;
#pragma unroll
        for (int s = 0; s < Sn; s++) { l[s] = __expf(l[s] - m); sum += l[s]; }
        float r = 1.f / sum;
#pragma unroll
        for (int s = 0; s < Sn; s++) s_u3.attn[tid * Sn + s] = l[s] * r;
    }
    __syncthreads();

    // coalesced copy s_attn -> g_attn; build attn B-fragment table over dead s_xc
    for (int i = tid; i < 128 * Sn / 4; i += 256)
        ((float4*)(g_attn + tok0 * Sn))[i] = ((const float4*)s_u3.attn)[i];
#pragma unroll
    for (int i = 0; i < 8; i++) {
        int e = tid + i * 256;               // 0..2047
        int ks = e >> 7, rem = e & 127;
        int h = rem >> 6, reg = (rem >> 5) & 1, L = rem & 31;
        int t = ks * 8 + (L & 3) + reg * 4;
        int s = h * 8 + (L >> 2);
        s_u2.bfa[e] = f2tf32(s_u3.attn[t * Sn + s]);
    }
    __syncthreads();   // s_u3.attn now dead; s_u3.comb usable

    // -------- Phase 2: G^T[d,s] = sum_t x[t,d] attn[t,s] via tf32 MMA --------
    // Chunk loop over output dims (32/chunk). Warp (mtile, h, kq):
    //   mtile = warp&1 (16-dim half), h = (warp>>1)&1 (8-splat half),
    //   kq = warp>>2 (64-token half). k-halves combined via s_u3.comb.
    int b = (int)(tok0 / Tn);
    int p = (int)((tok0 % Tn) / 128);
    float* gp = g_Gpart + ((long long)(b * PARTS + p) * Sn * Dn);
    int mtile = warp & 1, hh = (warp >> 1) & 1, kq = warp >> 2;
    int dloc = mtile * 16;

#pragma unroll 1
    for (int c = 0; c < 16; c++) {
        // stage x chunk as tf32 (same pattern as phase 1, no x2)
#pragma unroll
        for (int i = 0; i < 4; i++) {
            int row = (tid >> 3) + i * 32, c4 = tid & 7;
            float4 v = ((const float4*)(xb + (long long)row * Dn))[c * 8 + c4];
            float4 t;
            t.x = __uint_as_float(f2tf32(v.x));
            t.y = __uint_as_float(f2tf32(v.y));
            t.z = __uint_as_float(f2tf32(v.z));
            t.w = __uint_as_float(f2tf32(v.w));
            *(float4*)&s_x[row * 36 + c4 * 4] = t;
        }
        __syncthreads();

        float cG[4] = {0.f, 0.f, 0.f, 0.f};
#pragma unroll
        for (int j = 0; j < 8; j++) {
            int ks = kq * 8 + j;
            int t0 = ks * 8;
            // A[m=dim][k=token] = s_x[token*36 + dim] (transposed access)
            unsigned a0 = __float_as_uint(s_x[(t0 + tg)     * 36 + dloc + gid]);
            unsigned a1 = __float_as_uint(s_x[(t0 + tg)     * 36 + dloc + gid + 8]);
            unsigned a2 = __float_as_uint(s_x[(t0 + tg + 4) * 36 + dloc + gid]);
            unsigned a3 = __float_as_uint(s_x[(t0 + tg + 4) * 36 + dloc + gid + 8]);
            unsigned b0 = s_u2.bfa[ks * 128 + hh * 64 + lane];
            unsigned b1 = s_u2.bfa[ks * 128 + hh * 64 + 32 + lane];
            mma_tf32(cG, a0, a1, a2, a3, b0, b1);
        }
        // combine k-halves: warps 4..7 publish, warps 0..3 add + store
        if (kq == 1) {
            float* cb = &s_u3.comb[((warp - 4) * 32 + lane) * 4];
            cb[0] = cG[0]; cb[1] = cG[1]; cb[2] = cG[2]; cb[3] = cG[3];
        }
        __syncthreads();
        if (kq == 0) {
            const float* cb = &s_u3.comb[(warp * 32 + lane) * 4];
            float c0 = cG[0] + cb[0], c1 = cG[1] + cb[1];
            float c2 = cG[2] + cb[2], c3 = cG[3] + cb[3];
            int s0 = hh * 8 + 2 * tg;
            int d  = c * 32 + dloc + gid;
            gp[(long long)s0       * Dn + d]     = c0;
            gp[(long long)(s0 + 1) * Dn + d]     = c1;
            gp[(long long)s0       * Dn + d + 8] = c2;
            gp[(long long)(s0 + 1) * Dn + d + 8] = c3;
        }
    }
}

// ---------------------------------------------------------------------------
// Kernel 2: reduce 64 partials -> G. 32768 outputs. Grid 128 x 256 thr.
// ---------------------------------------------------------------------------
__global__ void k_reduce() {
    int idx = blockIdx.x * blockDim.x + threadIdx.x;   // < Bn*Sn*Dn = 32768
    int b = idx >> 13;
    int r = idx & 8191;
    float sum = 0.f;
#pragma unroll
    for (int p = 0; p < PARTS; p++)
        sum += g_Gpart[(long long)(b * PARTS + p) * (Sn * Dn) + r];
    g_G[idx] = sum;
}

// ---------------------------------------------------------------------------
// Kernel 3: small GEMM out[row][k] = sum_d in[row][d] * W[k][d], rows = 64.
// Round-6 measured-best (7.17us): grid (64,4) x 256 thr, 16 in-rows in smem,
// warp-per-column, plain float4 FMA, reduce-scatter finish.
// ---------------------------------------------------------------------------
__global__ __launch_bounds__(256) void k_small_gemm(const float* __restrict__ W, int stage) {
    const float* in  = (stage == 0) ? g_G : g_H;
    float*       out = (stage == 0) ? g_H : g_M;
    __shared__ float4 s_in[16 * 128];        // 32 KB

    int tid = threadIdx.x, warp = tid >> 5, lane = tid & 31;
    int kc = blockIdx.x;                     // 0..63 column chunk
    int b  = blockIdx.y;                     // 0..3 batch

    const float4* src = (const float4*)(in + (long long)b * 16 * Dn);
#pragma unroll
    for (int i = 0; i < 8; i++) s_in[tid + i * 256] = src[tid + i * 256];
    __syncthreads();

    int k = kc * 8 + warp;                   // output column, 0..511
    const float4* wr = (const float4*)(W + (long long)k * Dn);
    float4 w0 = wr[lane], w1 = wr[lane + 32], w2 = wr[lane + 64], w3 = wr[lane + 96];

    float acc[16];
#pragma unroll
    for (int r = 0; r < 16; r++) {
        float4 g0 = s_in[r * 128 + lane];
        float4 g1 = s_in[r * 128 + lane + 32];
        float4 g2 = s_in[r * 128 + lane + 64];
        float4 g3 = s_in[r * 128 + lane + 96];
        acc[r] = w0.x*g0.x + w0.y*g0.y + w0.z*g0.z + w0.w*g0.w
               + w1.x*g1.x + w1.y*g1.y + w1.z*g1.z + w1.w*g1.w
               + w2.x*g2.x + w2.y*g2.y + w2.z*g2.z + w2.w*g2.w
               + w3.x*g3.x + w3.y*g3.y + w3.z*g3.z + w3.w*g3.w;
    }
    float val = reduce16_scatter(acc, lane);
    int row = (lane >> 1) & 15;
    if ((lane & 1) == 0)
        out[(long long)(b * 16 + row) * Dn + k] = val;
}

// ---------------------------------------------------------------------------
// Kernel 4: y[t,:] = sum_s attn[t,s] * M[b,s,:]. Grid 256 x 256 thr,
// 128 tokens/block; thread owns 4 dims (float4), half=tid>>7 picks 64 tokens;
// M columns in 16 float4 registers; STG.128 stores.
// ---------------------------------------------------------------------------
__global__ __launch_bounds__(256) void k_out(float* __restrict__ y) {
    __shared__ float s_a[128 * Sn];          // 8 KB attn tile
    int tid = threadIdx.x;
    long long tok0 = (long long)blockIdx.x * 128;
    int b = (int)(tok0 / Tn);

#pragma unroll
    for (int i = 0; i < 2; i++)
        ((float4*)s_a)[tid + i * 256] = ((const float4*)(g_attn + tok0 * Sn))[tid + i * 256];
    __syncthreads();

    int dg = tid & 127, half = tid >> 7;
    const float* Mb = g_M + (long long)b * Sn * Dn;
    float4 m[Sn];
#pragma unroll
    for (int s = 0; s < Sn; s++) m[s] = ((const float4*)(Mb + s * Dn))[dg];

    float* yb = y + (tok0 + half * 64) * Dn;
#pragma unroll 2
    for (int t = 0; t < 64; t++) {
        const float4* ar = (const float4*)&s_a[(half * 64 + t) * Sn];
        float4 o; o.x = 0.f; o.y = 0.f; o.z = 0.f; o.w = 0.f;
#pragma unroll
        for (int q = 0; q < 4; q++) {
            float4 a = ar[q];
#pragma unroll
            for (int j = 0; j < 4; j++) {
                float av = (j == 0) ? a.x : (j == 1) ? a.y : (j == 2) ? a.z : a.w;
                float4 mv = m[q * 4 + j];
                o.x += av * mv.x; o.y += av * mv.y;
                o.z += av * mv.z; o.w += av * mv.w;
            }
        }
        ((float4*)(yb + (long long)t * Dn))[dg] = o;
    }
}

// ---------------------------------------------------------------------------
extern "C" void kernel_launch(void* const* d_in, const int* in_sizes, int n_in,
                              void* d_out, int out_size) {
    (void)in_sizes; (void)n_in; (void)out_size;
    const float* x          = (const float*)d_in[0];   // [B,T,D]
    const float* centers    = (const float*)d_in[1];   // [S,D]
    const float* log_scales = (const float*)d_in[2];   // [S]
    const float* Wv         = (const float*)d_in[3];   // [D,D]
    const float* Wo         = (const float*)d_in[4];   // [D,D]
    float* y = (float*)d_out;                          // [B,T,D] fp32

    k_attn_g<<<256, 256>>>(x, centers, log_scales);
    k_reduce<<<128, 256>>>();
    k_small_gemm<<<dim3(64, 4), 256>>>(Wv, 0);
    k_small_gemm<<<dim3(64, 4), 256>>>(Wo, 1);
    k_out<<<256, 256>>>(y);
}

// round 11
// speedup vs baseline: 1.0511x; 1.0511x over previous
#include <cuda_runtime.h>
#include <math.h>

#define Bn 4
#define Tn 8192
#define Dn 512
#define Sn 16
#define PARTS 64   // 256 blocks / 4 batches in the fused attn+G pass

// Scratch (static device globals — allocation-free per harness rules)
__device__ float g_attn [Bn*Tn*Sn];          // 2 MB
__device__ float g_Gpart[Bn*PARTS*Sn*Dn];    // 8 MB
__device__ float g_G    [Bn*Sn*Dn];
__device__ float g_Wf   [Dn*Dn];             // 1 MB: Wf = Wo . Wv
__device__ float g_M    [Bn*Sn*Dn];

__device__ __forceinline__ unsigned f2tf32(float f) {
    unsigned r; asm("cvt.rna.tf32.f32 %0, %1;" : "=r"(r) : "f"(f));
    return r;
}

__device__ __forceinline__ void mma_tf32(float c[4],
    unsigned a0, unsigned a1, unsigned a2, unsigned a3,
    unsigned b0, unsigned b1) {
    asm("mma.sync.aligned.m16n8k8.row.col.f32.tf32.tf32.f32 "
        "{%0,%1,%2,%3}, {%4,%5,%6,%7}, {%8,%9}, {%0,%1,%2,%3};"
        : "+f"(c[0]), "+f"(c[1]), "+f"(c[2]), "+f"(c[3])
        : "r"(a0), "r"(a1), "r"(a2), "r"(a3), "r"(b0), "r"(b1));
}

// 8-lane reduction (lanes differing in bits 0..2)
__device__ __forceinline__ float red8(float v) {
    v += __shfl_xor_sync(0xffffffffu, v, 1);
    v += __shfl_xor_sync(0xffffffffu, v, 2);
    v += __shfl_xor_sync(0xffffffffu, v, 4);
    return v;
}

// Reduce acc[16] with 16 shuffles; result for index (lane>>1)&15 on even lanes.
__device__ __forceinline__ float reduce16_scatter(float* acc, int lane) {
#pragma unroll
    for (int step = 16, n = 8; n >= 1; step >>= 1, n >>= 1) {
        bool hi = (lane & step) != 0;
#pragma unroll
        for (int i = 0; i < n; i++) {
            float send = hi ? acc[i] : acc[i + n];
            float recv = __shfl_xor_sync(0xffffffffu, send, step);
            acc[i] = (hi ? acc[i + n] : acc[i]) + recv;
        }
    }
    float v = acc[0];
    v += __shfl_xor_sync(0xffffffffu, v, 1);
    return v;
}

// ---------------------------------------------------------------------------
// Kernel 1 (fused): blocks 0..255: attention weights (tf32 MMA for xc; x2
// folded into staging) + partial G = attn^T x (fp32, coalesced — round-8
// measured-best). Blocks 256..383: Wf = Wo . Wv (4 rows each), fully
// overlapped with the attention work.
// ---------------------------------------------------------------------------
__global__ __launch_bounds__(256) void k_attn_g(const float* __restrict__ x,
                                                const float* __restrict__ centers,
                                                const float* __restrict__ log_scales,
                                                const float* __restrict__ Wv,
                                                const float* __restrict__ Wo) {
    __shared__ float    s_x   [128 * 36];    // tf32 x chunk, padded (18 KB)
    __shared__ unsigned s_bf  [512];         // B fragments (centers) per chunk (2 KB)
    __shared__ float    s_xc  [128 * 17];    // XC, padded (8.7 KB)
    __shared__ float    s_attn[128 * Sn];    // 8 KB
    __shared__ float    s_x2  [128];
    __shared__ float    s_part[256];
    __shared__ float    s_inv [Sn], s_bias[Sn];

    int tid  = threadIdx.x;

    // ================= Wf blocks: Wf[i][j] = sum_e Wo[i][e] * Wv[e][j] ======
    if (blockIdx.x >= 256) {
        int i0 = (blockIdx.x - 256) * 4;     // 4 output rows per block
        float* s_wo = s_x;                   // 4*512 floats = 8 KB (fits)
        for (int i = tid; i < 512; i += 256)
            ((float4*)s_wo)[i] = ((const float4*)(Wo + (long long)i0 * Dn))[i];
        __syncthreads();
        int j = tid;                         // columns j and j+256
        float a0=0.f,a1=0.f,a2=0.f,a3=0.f;
        float b0=0.f,b1=0.f,b2=0.f,b3=0.f;
#pragma unroll 4
        for (int e = 0; e < 512; e++) {
            float wv0 = Wv[(long long)e * Dn + j];
            float wv1 = Wv[(long long)e * Dn + j + 256];
            float w0 = s_wo[0*512+e], w1 = s_wo[1*512+e];
            float w2 = s_wo[2*512+e], w3 = s_wo[3*512+e];
            a0 += w0*wv0; b0 += w0*wv1;
            a1 += w1*wv0; b1 += w1*wv1;
            a2 += w2*wv0; b2 += w2*wv1;
            a3 += w3*wv0; b3 += w3*wv1;
        }
        g_Wf[(long long)(i0+0)*Dn + j] = a0; g_Wf[(long long)(i0+0)*Dn + j+256] = b0;
        g_Wf[(long long)(i0+1)*Dn + j] = a1; g_Wf[(long long)(i0+1)*Dn + j+256] = b1;
        g_Wf[(long long)(i0+2)*Dn + j] = a2; g_Wf[(long long)(i0+2)*Dn + j+256] = b2;
        g_Wf[(long long)(i0+3)*Dn + j] = a3; g_Wf[(long long)(i0+3)*Dn + j+256] = b3;
        return;
    }

    // ================= attention blocks (round-8 measured-best) =============
    int warp = tid >> 5, lane = tid & 31;
    int gid  = lane >> 2, tg = lane & 3;     // mma fragment coords
    long long tok0 = (long long)blockIdx.x * 128;
    const float* xb = x + tok0 * Dn;

    // ---- scale/bias precompute: c2 via 16 threads per splat ----
    {
        int sp = tid >> 4, p16 = tid & 15;
        const float4* cr = (const float4*)(centers + (long long)sp * Dn);
        float c2 = 0.f;
#pragma unroll
        for (int j = 0; j < 8; j++) {
            float4 v = cr[p16 + j * 16];
            c2 += v.x * v.x + v.y * v.y + v.z * v.z + v.w * v.w;
        }
        s_part[tid] = c2;
        __syncthreads();
        if (tid < Sn) {
            float c2t = 0.f;
#pragma unroll
            for (int k = 0; k < 16; k++) c2t += s_part[tid * 16 + k];
            float s = expf(log_scales[tid]);
            s = fminf(fmaxf(s, 0.1f), 2.0f);
            float inv = -0.5f / (s * s);
            s_inv[tid]  = inv;
            s_bias[tid] = inv * c2t;
        }
    }

    // ---- Phase 1: XC = x . centers^T via tf32 mma; x2 folded into staging ----
    float xcacc[2][4];
#pragma unroll
    for (int h = 0; h < 2; h++)
#pragma unroll
        for (int r = 0; r < 4; r++) xcacc[h][r] = 0.f;
    float x2p[4] = {0.f, 0.f, 0.f, 0.f};     // partial x2 for rows (tid>>3)+32i, col tid&7
    int tlw = warp * 16;                     // warp's m-tile token base

#pragma unroll 1
    for (int c = 0; c < 16; c++) {
        // stage x chunk (cols c*32..+31) as tf32, padded stride 36; fold x2
#pragma unroll
        for (int i = 0; i < 4; i++) {
            int row = (tid >> 3) + i * 32, c4 = tid & 7;
            float4 v = ((const float4*)(xb + (long long)row * Dn))[c * 8 + c4];
            x2p[i] += v.x * v.x + v.y * v.y + v.z * v.z + v.w * v.w;
            float4 t;
            t.x = __uint_as_float(f2tf32(v.x));
            t.y = __uint_as_float(f2tf32(v.y));
            t.z = __uint_as_float(f2tf32(v.z));
            t.w = __uint_as_float(f2tf32(v.w));
            *(float4*)&s_x[row * 36 + c4 * 4] = t;
        }
        // B fragments for this chunk: [kit8][h][which][lane]
#pragma unroll
        for (int i = 0; i < 2; i++) {
            int e = tid + i * 256;           // 0..511
            int kit8 = e >> 7, rem = e & 127;
            int h = rem >> 6, which = (rem >> 5) & 1, L = rem & 31;
            int k  = c * 32 + kit8 * 8 + (L & 3) + which * 4;
            int sp = h * 8 + (L >> 2);
            s_bf[e] = f2tf32(centers[(long long)sp * Dn + k]);
        }
        __syncthreads();
        // 4 k-iterations of m16n8k8 per n-half
#pragma unroll
        for (int kit8 = 0; kit8 < 4; kit8++) {
            int kb = kit8 * 8;
            unsigned a0 = __float_as_uint(s_x[(tlw + gid)     * 36 + kb + tg]);
            unsigned a1 = __float_as_uint(s_x[(tlw + gid + 8) * 36 + kb + tg]);
            unsigned a2 = __float_as_uint(s_x[(tlw + gid)     * 36 + kb + tg + 4]);
            unsigned a3 = __float_as_uint(s_x[(tlw + gid + 8) * 36 + kb + tg + 4]);
#pragma unroll
            for (int h = 0; h < 2; h++) {
                unsigned b0 = s_bf[kit8 * 128 + h * 64 + lane];
                unsigned b1 = s_bf[kit8 * 128 + h * 64 + 32 + lane];
                mma_tf32(xcacc[h], a0, a1, a2, a3, b0, b1);
            }
        }
        __syncthreads();
    }

    // write XC fragments to padded smem
#pragma unroll
    for (int h = 0; h < 2; h++) {
        int col = h * 8 + tg * 2;
        s_xc[(tlw + gid)     * 17 + col]     = xcacc[h][0];
        s_xc[(tlw + gid)     * 17 + col + 1] = xcacc[h][1];
        s_xc[(tlw + gid + 8) * 17 + col]     = xcacc[h][2];
        s_xc[(tlw + gid + 8) * 17 + col + 1] = xcacc[h][3];
    }
    // finish x2: threads sharing a row differ in lane bits 0..2
#pragma unroll
    for (int i = 0; i < 4; i++) {
        float v = red8(x2p[i]);
        if ((tid & 7) == 0) s_x2[(tid >> 3) + i * 32] = v;
    }
    __syncthreads();

    // per-token softmax (threads 0..127)
    if (tid < 128) {
        float x2 = s_x2[tid];
        float l[Sn];
        float m = -1e30f;
#pragma unroll
        for (int s = 0; s < Sn; s++) {
            l[s] = s_inv[s] * (x2 - 2.f * s_xc[tid * 17 + s]) + s_bias[s];
            m = fmaxf(m, l[s]);
        }
        float sum = 0.f;
#pragma unroll
        for (int s = 0; s < Sn; s++) { l[s] = __expf(l[s] - m); sum += l[s]; }
        float r = 1.f / sum;
#pragma unroll
        for (int s = 0; s < Sn; s++) s_attn[tid * Sn + s] = l[s] * r;
    }
    __syncthreads();

    // coalesced copy s_attn -> g_attn
    for (int i = tid; i < 128 * Sn / 4; i += 256)
        ((float4*)(g_attn + tok0 * Sn))[i] = ((const float4*)s_attn)[i];

    // -------- Phase 2: G partial over this block's 128 tokens (fp32) --------
    float2 accG[Sn];
#pragma unroll
    for (int s = 0; s < Sn; s++) { accG[s].x = 0.f; accG[s].y = 0.f; }

#pragma unroll 4
    for (int t = 0; t < 128; t++) {
        float2 xv = ((const float2*)(xb + (long long)t * Dn))[tid];   // d = 2*tid, 2*tid+1
        const float4* ar = (const float4*)&s_attn[t * Sn];
#pragma unroll
        for (int q = 0; q < 4; q++) {
            float4 a = ar[q];
            accG[q*4+0].x += a.x * xv.x; accG[q*4+0].y += a.x * xv.y;
            accG[q*4+1].x += a.y * xv.x; accG[q*4+1].y += a.y * xv.y;
            accG[q*4+2].x += a.z * xv.x; accG[q*4+2].y += a.z * xv.y;
            accG[q*4+3].x += a.w * xv.x; accG[q*4+3].y += a.w * xv.y;
        }
    }

    int b = (int)(tok0 / Tn);
    int p = (int)((tok0 % Tn) / 128);
    float* gp = g_Gpart + ((long long)(b * PARTS + p) * Sn * Dn);
#pragma unroll
    for (int s = 0; s < Sn; s++)
        ((float2*)(gp + s * Dn))[tid] = accG[s];
}

// ---------------------------------------------------------------------------
// Kernel 2: reduce 64 partials -> G. 32768 outputs. Grid 128 x 256 thr.
// ---------------------------------------------------------------------------
__global__ void k_reduce() {
    int idx = blockIdx.x * blockDim.x + threadIdx.x;   // < Bn*Sn*Dn = 32768
    int b = idx >> 13;
    int r = idx & 8191;
    float sum = 0.f;
#pragma unroll
    for (int p = 0; p < PARTS; p++)
        sum += g_Gpart[(long long)(b * PARTS + p) * (Sn * Dn) + r];
    g_G[idx] = sum;
}

// ---------------------------------------------------------------------------
// Kernel 3: single small GEMM M[row][k] = sum_d G[row][d] * Wf[k][d], rows=64.
// Round-6 measured-best body: grid (64,4) x 256 thr, 16 in-rows in smem,
// warp-per-column, plain float4 FMA, reduce-scatter finish.
// ---------------------------------------------------------------------------
__global__ __launch_bounds__(256) void k_small_gemm() {
    __shared__ float4 s_in[16 * 128];        // 32 KB

    int tid = threadIdx.x, warp = tid >> 5, lane = tid & 31;
    int kc = blockIdx.x;                     // 0..63 column chunk
    int b  = blockIdx.y;                     // 0..3 batch

    const float4* src = (const float4*)(g_G + (long long)b * 16 * Dn);
#pragma unroll
    for (int i = 0; i < 8; i++) s_in[tid + i * 256] = src[tid + i * 256];
    __syncthreads();

    int k = kc * 8 + warp;                   // output column, 0..511
    const float4* wr = (const float4*)(g_Wf + (long long)k * Dn);
    float4 w0 = wr[lane], w1 = wr[lane + 32], w2 = wr[lane + 64], w3 = wr[lane + 96];

    float acc[16];
#pragma unroll
    for (int r = 0; r < 16; r++) {
        float4 g0 = s_in[r * 128 + lane];
        float4 g1 = s_in[r * 128 + lane + 32];
        float4 g2 = s_in[r * 128 + lane + 64];
        float4 g3 = s_in[r * 128 + lane + 96];
        acc[r] = w0.x*g0.x + w0.y*g0.y + w0.z*g0.z + w0.w*g0.w
               + w1.x*g1.x + w1.y*g1.y + w1.z*g1.z + w1.w*g1.w
               + w2.x*g2.x + w2.y*g2.y + w2.z*g2.z + w2.w*g2.w
               + w3.x*g3.x + w3.y*g3.y + w3.z*g3.z + w3.w*g3.w;
    }
    float val = reduce16_scatter(acc, lane);
    int row = (lane >> 1) & 15;
    if ((lane & 1) == 0)
        g_M[(long long)(b * 16 + row) * Dn + k] = val;
}

// ---------------------------------------------------------------------------
// Kernel 4: y[t,:] = sum_s attn[t,s] * M[b,s,:]. Grid 256 x 256 thr,
// 128 tokens/block; thread owns 4 dims (float4), half=tid>>7 picks 64 tokens;
// M columns in 16 float4 registers; STG.128 stores.
// ---------------------------------------------------------------------------
__global__ __launch_bounds__(256) void k_out(float* __restrict__ y) {
    __shared__ float s_a[128 * Sn];          // 8 KB attn tile
    int tid = threadIdx.x;
    long long tok0 = (long long)blockIdx.x * 128;
    int b = (int)(tok0 / Tn);

#pragma unroll
    for (int i = 0; i < 2; i++)
        ((float4*)s_a)[tid + i * 256] = ((const float4*)(g_attn + tok0 * Sn))[tid + i * 256];
    __syncthreads();

    int dg = tid & 127, half = tid >> 7;
    const float* Mb = g_M + (long long)b * Sn * Dn;
    float4 m[Sn];
#pragma unroll
    for (int s = 0; s < Sn; s++) m[s] = ((const float4*)(Mb + s * Dn))[dg];

    float* yb = y + (tok0 + half * 64) * Dn;
#pragma unroll 2
    for (int t = 0; t < 64; t++) {
        const float4* ar = (const float4*)&s_a[(half * 64 + t) * Sn];
        float4 o; o.x = 0.f; o.y = 0.f; o.z = 0.f; o.w = 0.f;
#pragma unroll
        for (int q = 0; q < 4; q++) {
            float4 a = ar[q];
#pragma unroll
            for (int j = 0; j < 4; j++) {
                float av = (j == 0) ? a.x : (j == 1) ? a.y : (j == 2) ? a.z : a.w;
                float4 mv = m[q * 4 + j];
                o.x += av * mv.x; o.y += av * mv.y;
                o.z += av * mv.z; o.w += av * mv.w;
            }
        }
        ((float4*)(yb + (long long)t * Dn))[dg] = o;
    }
}

// ---------------------------------------------------------------------------
extern "C" void kernel_launch(void* const* d_in, const int* in_sizes, int n_in,
                              void* d_out, int out_size) {
    (void)in_sizes; (void)n_in; (void)out_size;
    const float* x          = (const float*)d_in[0];   // [B,T,D]
    const float* centers    = (const float*)d_in[1];   // [S,D]
    const float* log_scales = (const float*)d_in[2];   // [S]
    const float* Wv         = (const float*)d_in[3];   // [D,D]
    const float* Wo         = (const float*)d_in[4];   // [D,D]
    float* y = (float*)d_out;                          // [B,T,D] fp32

    k_attn_g<<<384, 256>>>(x, centers, log_scales, Wv, Wo);
    k_reduce<<<128, 256>>>();
    k_small_gemm<<<dim3(64, 4), 256>>>();
    k_out<<<256, 256>>>(y);
}

// round 12
// speedup vs baseline: 1.3263x; 1.2618x over previous
#include <cuda_runtime.h>
#include <math.h>

#define Bn 4
#define Tn 8192
#define Dn 512
#define Sn 16
#define PARTS 64   // 256 blocks / 4 batches in the fused attn+G pass

// Scratch (static device globals — allocation-free per harness rules)
__device__ float g_attn [Bn*Tn*Sn];          // 2 MB
__device__ float g_Gpart[Bn*PARTS*Sn*Dn];    // 8 MB
__device__ float g_G    [Bn*Sn*Dn];
__device__ float g_H    [Bn*Sn*Dn];
__device__ float g_M    [Bn*Sn*Dn];

__device__ __forceinline__ unsigned f2tf32(float f) {
    unsigned r; asm("cvt.rna.tf32.f32 %0, %1;" : "=r"(r) : "f"(f));
    return r;
}

__device__ __forceinline__ void mma_tf32(float c[4],
    unsigned a0, unsigned a1, unsigned a2, unsigned a3,
    unsigned b0, unsigned b1) {
    asm("mma.sync.aligned.m16n8k8.row.col.f32.tf32.tf32.f32 "
        "{%0,%1,%2,%3}, {%4,%5,%6,%7}, {%8,%9}, {%0,%1,%2,%3};"
        : "+f"(c[0]), "+f"(c[1]), "+f"(c[2]), "+f"(c[3])
        : "r"(a0), "r"(a1), "r"(a2), "r"(a3), "r"(b0), "r"(b1));
}

// 8-lane reduction (lanes differing in bits 0..2)
__device__ __forceinline__ float red8(float v) {
    v += __shfl_xor_sync(0xffffffffu, v, 1);
    v += __shfl_xor_sync(0xffffffffu, v, 2);
    v += __shfl_xor_sync(0xffffffffu, v, 4);
    return v;
}

// Reduce acc[16] with 16 shuffles; result for index (lane>>1)&15 on even lanes.
__device__ __forceinline__ float reduce16_scatter(float* acc, int lane) {
#pragma unroll
    for (int step = 16, n = 8; n >= 1; step >>= 1, n >>= 1) {
        bool hi = (lane & step) != 0;
#pragma unroll
        for (int i = 0; i < n; i++) {
            float send = hi ? acc[i] : acc[i + n];
            float recv = __shfl_xor_sync(0xffffffffu, send, step);
            acc[i] = (hi ? acc[i + n] : acc[i]) + recv;
        }
    }
    float v = acc[0];
    v += __shfl_xor_sync(0xffffffffu, v, 1);
    return v;
}

// ---------------------------------------------------------------------------
// Kernel 1 (fused): attention weights (tf32 MMA for xc; x2 folded into the
// staging loop, fp32) + partial G = attn^T x (fp32, coalesced).
// Round-8 measured-best. Grid 256 x 256 thr, 128 tokens/block.
// ---------------------------------------------------------------------------
__global__ __launch_bounds__(256) void k_attn_g(const float* __restrict__ x,
                                                const float* __restrict__ centers,
                                                const float* __restrict__ log_scales) {
    __shared__ float    s_x   [128 * 36];    // tf32 x chunk, padded (18 KB)
    __shared__ unsigned s_bf  [512];         // B fragments (centers) per chunk (2 KB)
    __shared__ float    s_xc  [128 * 17];    // XC, padded (8.7 KB)
    __shared__ float    s_attn[128 * Sn];    // 8 KB
    __shared__ float    s_x2  [128];
    __shared__ float    s_part[256];
    __shared__ float    s_inv [Sn], s_bias[Sn];

    int tid  = threadIdx.x;
    int warp = tid >> 5, lane = tid & 31;
    int gid  = lane >> 2, tg = lane & 3;     // mma fragment coords
    long long tok0 = (long long)blockIdx.x * 128;
    const float* xb = x + tok0 * Dn;

    // ---- scale/bias precompute: c2 via 16 threads per splat ----
    {
        int sp = tid >> 4, p16 = tid & 15;
        const float4* cr = (const float4*)(centers + (long long)sp * Dn);
        float c2 = 0.f;
#pragma unroll
        for (int j = 0; j < 8; j++) {
            float4 v = cr[p16 + j * 16];
            c2 += v.x * v.x + v.y * v.y + v.z * v.z + v.w * v.w;
        }
        s_part[tid] = c2;
        __syncthreads();
        if (tid < Sn) {
            float c2t = 0.f;
#pragma unroll
            for (int k = 0; k < 16; k++) c2t += s_part[tid * 16 + k];
            float s = expf(log_scales[tid]);
            s = fminf(fmaxf(s, 0.1f), 2.0f);
            float inv = -0.5f / (s * s);
            s_inv[tid]  = inv;
            s_bias[tid] = inv * c2t;
        }
    }

    // ---- Phase 1: XC = x . centers^T via tf32 mma; x2 folded into staging ----
    float xcacc[2][4];
#pragma unroll
    for (int h = 0; h < 2; h++)
#pragma unroll
        for (int r = 0; r < 4; r++) xcacc[h][r] = 0.f;
    float x2p[4] = {0.f, 0.f, 0.f, 0.f};     // partial x2 for rows (tid>>3)+32i, col tid&7
    int tlw = warp * 16;                     // warp's m-tile token base

#pragma unroll 1
    for (int c = 0; c < 16; c++) {
        // stage x chunk (cols c*32..+31) as tf32, padded stride 36; fold x2
#pragma unroll
        for (int i = 0; i < 4; i++) {
            int row = (tid >> 3) + i * 32, c4 = tid & 7;
            float4 v = ((const float4*)(xb + (long long)row * Dn))[c * 8 + c4];
            x2p[i] += v.x * v.x + v.y * v.y + v.z * v.z + v.w * v.w;
            float4 t;
            t.x = __uint_as_float(f2tf32(v.x));
            t.y = __uint_as_float(f2tf32(v.y));
            t.z = __uint_as_float(f2tf32(v.z));
            t.w = __uint_as_float(f2tf32(v.w));
            *(float4*)&s_x[row * 36 + c4 * 4] = t;
        }
        // B fragments for this chunk: [kit8][h][which][lane]
#pragma unroll
        for (int i = 0; i < 2; i++) {
            int e = tid + i * 256;           // 0..511
            int kit8 = e >> 7, rem = e & 127;
            int h = rem >> 6, which = (rem >> 5) & 1, L = rem & 31;
            int k  = c * 32 + kit8 * 8 + (L & 3) + which * 4;
            int sp = h * 8 + (L >> 2);
            s_bf[e] = f2tf32(centers[(long long)sp * Dn + k]);
        }
        __syncthreads();
        // 4 k-iterations of m16n8k8 per n-half
#pragma unroll
        for (int kit8 = 0; kit8 < 4; kit8++) {
            int kb = kit8 * 8;
            unsigned a0 = __float_as_uint(s_x[(tlw + gid)     * 36 + kb + tg]);
            unsigned a1 = __float_as_uint(s_x[(tlw + gid + 8) * 36 + kb + tg]);
            unsigned a2 = __float_as_uint(s_x[(tlw + gid)     * 36 + kb + tg + 4]);
            unsigned a3 = __float_as_uint(s_x[(tlw + gid + 8) * 36 + kb + tg + 4]);
#pragma unroll
            for (int h = 0; h < 2; h++) {
                unsigned b0 = s_bf[kit8 * 128 + h * 64 + lane];
                unsigned b1 = s_bf[kit8 * 128 + h * 64 + 32 + lane];
                mma_tf32(xcacc[h], a0, a1, a2, a3, b0, b1);
            }
        }
        __syncthreads();
    }

    // write XC fragments to padded smem
#pragma unroll
    for (int h = 0; h < 2; h++) {
        int col = h * 8 + tg * 2;
        s_xc[(tlw + gid)     * 17 + col]     = xcacc[h][0];
        s_xc[(tlw + gid)     * 17 + col + 1] = xcacc[h][1];
        s_xc[(tlw + gid + 8) * 17 + col]     = xcacc[h][2];
        s_xc[(tlw + gid + 8) * 17 + col + 1] = xcacc[h][3];
    }
    // finish x2: threads sharing a row differ in lane bits 0..2
#pragma unroll
    for (int i = 0; i < 4; i++) {
        float v = red8(x2p[i]);
        if ((tid & 7) == 0) s_x2[(tid >> 3) + i * 32] = v;
    }
    __syncthreads();

    // per-token softmax (threads 0..127)
    if (tid < 128) {
        float x2 = s_x2[tid];
        float l[Sn];
        float m = -1e30f;
#pragma unroll
        for (int s = 0; s < Sn; s++) {
            l[s] = s_inv[s] * (x2 - 2.f * s_xc[tid * 17 + s]) + s_bias[s];
            m = fmaxf(m, l[s]);
        }
        float sum = 0.f;
#pragma unroll
        for (int s = 0; s < Sn; s++) { l[s] = __expf(l[s] - m); sum += l[s]; }
        float r = 1.f / sum;
#pragma unroll
        for (int s = 0; s < Sn; s++) s_attn[tid * Sn + s] = l[s] * r;
    }
    __syncthreads();

    // coalesced copy s_attn -> g_attn
    for (int i = tid; i < 128 * Sn / 4; i += 256)
        ((float4*)(g_attn + tok0 * Sn))[i] = ((const float4*)s_attn)[i];

    // -------- Phase 2: G partial over this block's 128 tokens (fp32) --------
    float2 accG[Sn];
#pragma unroll
    for (int s = 0; s < Sn; s++) { accG[s].x = 0.f; accG[s].y = 0.f; }

#pragma unroll 4
    for (int t = 0; t < 128; t++) {
        float2 xv = ((const float2*)(xb + (long long)t * Dn))[tid];   // d = 2*tid, 2*tid+1
        const float4* ar = (const float4*)&s_attn[t * Sn];
#pragma unroll
        for (int q = 0; q < 4; q++) {
            float4 a = ar[q];
            accG[q*4+0].x += a.x * xv.x; accG[q*4+0].y += a.x * xv.y;
            accG[q*4+1].x += a.y * xv.x; accG[q*4+1].y += a.y * xv.y;
            accG[q*4+2].x += a.z * xv.x; accG[q*4+2].y += a.z * xv.y;
            accG[q*4+3].x += a.w * xv.x; accG[q*4+3].y += a.w * xv.y;
        }
    }

    int b = (int)(tok0 / Tn);
    int p = (int)((tok0 % Tn) / 128);
    float* gp = g_Gpart + ((long long)(b * PARTS + p) * Sn * Dn);
#pragma unroll
    for (int s = 0; s < Sn; s++)
        ((float2*)(gp + s * Dn))[tid] = accG[s];
}

// ---------------------------------------------------------------------------
// Kernel 2: reduce 64 partials -> G. 32768 outputs. Grid 128 x 256 thr.
// ---------------------------------------------------------------------------
__global__ void k_reduce() {
    int idx = blockIdx.x * blockDim.x + threadIdx.x;   // < Bn*Sn*Dn = 32768
    int b = idx >> 13;
    int r = idx & 8191;
    float sum = 0.f;
#pragma unroll
    for (int p = 0; p < PARTS; p++)
        sum += g_Gpart[(long long)(b * PARTS + p) * (Sn * Dn) + r];
    g_G[idx] = sum;
}

// ---------------------------------------------------------------------------
// Kernel 3: small GEMM out[row][k] = sum_d in[row][d] * W[k][d], rows = 64.
// Round-6 measured-best (7.17us): grid (64,4) x 256 thr, 16 in-rows in smem,
// warp-per-column, plain float4 FMA, reduce-scatter finish.
// ---------------------------------------------------------------------------
__global__ __launch_bounds__(256) void k_small_gemm(const float* __restrict__ W, int stage) {
    const float* in  = (stage == 0) ? g_G : g_H;
    float*       out = (stage == 0) ? g_H : g_M;
    __shared__ float4 s_in[16 * 128];        // 32 KB

    int tid = threadIdx.x, warp = tid >> 5, lane = tid & 31;
    int kc = blockIdx.x;                     // 0..63 column chunk
    int b  = blockIdx.y;                     // 0..3 batch

    const float4* src = (const float4*)(in + (long long)b * 16 * Dn);
#pragma unroll
    for (int i = 0; i < 8; i++) s_in[tid + i * 256] = src[tid + i * 256];
    __syncthreads();

    int k = kc * 8 + warp;                   // output column, 0..511
    const float4* wr = (const float4*)(W + (long long)k * Dn);
    float4 w0 = wr[lane], w1 = wr[lane + 32], w2 = wr[lane + 64], w3 = wr[lane + 96];

    float acc[16];
#pragma unroll
    for (int r = 0; r < 16; r++) {
        float4 g0 = s_in[r * 128 + lane];
        float4 g1 = s_in[r * 128 + lane + 32];
        float4 g2 = s_in[r * 128 + lane + 64];
        float4 g3 = s_in[r * 128 + lane + 96];
        acc[r] = w0.x*g0.x + w0.y*g0.y + w0.z*g0.z + w0.w*g0.w
               + w1.x*g1.x + w1.y*g1.y + w1.z*g1.z + w1.w*g1.w
               + w2.x*g2.x + w2.y*g2.y + w2.z*g2.z + w2.w*g2.w
               + w3.x*g3.x + w3.y*g3.y + w3.z*g3.z + w3.w*g3.w;
    }
    float val = reduce16_scatter(acc, lane);
    int row = (lane >> 1) & 15;
    if ((lane & 1) == 0)
        out[(long long)(b * 16 + row) * Dn + k] = val;
}

// ---------------------------------------------------------------------------
// Kernel 4: y = attn . M via tf32 MMA. Grid 256 x 256 thr, 128 tokens/block.
// Warp owns a 16-token m-tile; loops 64 n-chunks of 8 dims; k = 16 splats
// (2 k-steps). attn (8 KB) + M (tf32, padded stride 520, 33 KB) in smem.
// B loads conflict-free (8*tg+gid covers 0..31); stores float2 coalesced.
// ---------------------------------------------------------------------------
__global__ __launch_bounds__(256) void k_out(float* __restrict__ y) {
    __shared__ float s_a[128 * Sn];          // attn tile as tf32 (8 KB)
    __shared__ float s_m[16 * 520];          // M tile as tf32, padded (33.3 KB)
    int tid = threadIdx.x, warp = tid >> 5, lane = tid & 31;
    int gid = lane >> 2, tg = lane & 3;
    long long tok0 = (long long)blockIdx.x * 128;
    int b = (int)(tok0 / Tn);

    // stage attn as tf32 (coalesced float4)
#pragma unroll
    for (int i = 0; i < 2; i++) {
        float4 v = ((const float4*)(g_attn + tok0 * Sn))[tid + i * 256];
        float4 t;
        t.x = __uint_as_float(f2tf32(v.x));
        t.y = __uint_as_float(f2tf32(v.y));
        t.z = __uint_as_float(f2tf32(v.z));
        t.w = __uint_as_float(f2tf32(v.w));
        ((float4*)s_a)[tid + i * 256] = t;
    }
    // stage M as tf32, padded stride 520
    const float* Mb = g_M + (long long)b * Sn * Dn;
#pragma unroll
    for (int i = 0; i < 8; i++) {
        int e = tid + i * 256;               // 0..2047 = 16 rows x 128 float4
        int r = e >> 7, c4 = e & 127;
        float4 v = ((const float4*)(Mb + (long long)r * Dn))[c4];
        float4 t;
        t.x = __uint_as_float(f2tf32(v.x));
        t.y = __uint_as_float(f2tf32(v.y));
        t.z = __uint_as_float(f2tf32(v.z));
        t.w = __uint_as_float(f2tf32(v.w));
        *(float4*)&s_m[r * 520 + c4 * 4] = t;
    }
    __syncthreads();

    int tlw = warp * 16;                     // warp's 16-token m-tile
    // A fragments, both k-steps, loaded once (16 scalar LDS per warp)
    unsigned a00 = __float_as_uint(s_a[(tlw + gid)     * Sn + tg]);
    unsigned a01 = __float_as_uint(s_a[(tlw + gid + 8) * Sn + tg]);
    unsigned a02 = __float_as_uint(s_a[(tlw + gid)     * Sn + tg + 4]);
    unsigned a03 = __float_as_uint(s_a[(tlw + gid + 8) * Sn + tg + 4]);
    unsigned a10 = __float_as_uint(s_a[(tlw + gid)     * Sn + tg + 8]);
    unsigned a11 = __float_as_uint(s_a[(tlw + gid + 8) * Sn + tg + 8]);
    unsigned a12 = __float_as_uint(s_a[(tlw + gid)     * Sn + tg + 12]);
    unsigned a13 = __float_as_uint(s_a[(tlw + gid + 8) * Sn + tg + 12]);

    float* y0 = y + (tok0 + tlw + gid)     * Dn + 2 * tg;
    float* y1 = y + (tok0 + tlw + gid + 8) * Dn + 2 * tg;

#pragma unroll 4
    for (int d0 = 0; d0 < Dn; d0 += 8) {
        float c[4] = {0.f, 0.f, 0.f, 0.f};
        unsigned b00 = __float_as_uint(s_m[ tg      * 520 + d0 + gid]);
        unsigned b01 = __float_as_uint(s_m[(tg + 4) * 520 + d0 + gid]);
        mma_tf32(c, a00, a01, a02, a03, b00, b01);
        unsigned b10 = __float_as_uint(s_m[(tg + 8)  * 520 + d0 + gid]);
        unsigned b11 = __float_as_uint(s_m[(tg + 12) * 520 + d0 + gid]);
        mma_tf32(c, a10, a11, a12, a13, b10, b11);
        *(float2*)(y0 + d0) = make_float2(c[0], c[1]);
        *(float2*)(y1 + d0) = make_float2(c[2], c[3]);
    }
}

// ---------------------------------------------------------------------------
extern "C" void kernel_launch(void* const* d_in, const int* in_sizes, int n_in,
                              void* d_out, int out_size) {
    (void)in_sizes; (void)n_in; (void)out_size;
    const float* x          = (const float*)d_in[0];   // [B,T,D]
    const float* centers    = (const float*)d_in[1];   // [S,D]
    const float* log_scales = (const float*)d_in[2];   // [S]
    const float* Wv         = (const float*)d_in[3];   // [D,D]
    const float* Wo         = (const float*)d_in[4];   // [D,D]
    float* y = (float*)d_out;                          // [B,T,D] fp32

    k_attn_g<<<256, 256>>>(x, centers, log_scales);
    k_reduce<<<128, 256>>>();
    k_small_gemm<<<dim3(64, 4), 256>>>(Wv, 0);
    k_small_gemm<<<dim3(64, 4), 256>>>(Wo, 1);
    k_out<<<256, 256>>>(y);
}

// round 13
// speedup vs baseline: 1.4685x; 1.1073x over previous
#include <cuda_runtime.h>
#include <math.h>

#define Bn 4
#define Tn 8192
#define Dn 512
#define Sn 16
#define PARTS 64   // 256 blocks / 4 batches in the fused attn+G pass

// Scratch (static device globals — allocation-free per harness rules)
__device__ float g_attn [Bn*Tn*Sn];          // 2 MB
__device__ float g_Gpart[Bn*PARTS*Sn*Dn];    // 8 MB
__device__ float g_G    [Bn*Sn*Dn];
__device__ float g_H    [Bn*Sn*Dn];
__device__ float g_M    [Bn*Sn*Dn];

__device__ __forceinline__ unsigned f2tf32(float f) {
    unsigned r; asm("cvt.rna.tf32.f32 %0, %1;" : "=r"(r) : "f"(f));
    return r;
}

__device__ __forceinline__ void mma_tf32(float c[4],
    unsigned a0, unsigned a1, unsigned a2, unsigned a3,
    unsigned b0, unsigned b1) {
    asm("mma.sync.aligned.m16n8k8.row.col.f32.tf32.tf32.f32 "
        "{%0,%1,%2,%3}, {%4,%5,%6,%7}, {%8,%9}, {%0,%1,%2,%3};"
        : "+f"(c[0]), "+f"(c[1]), "+f"(c[2]), "+f"(c[3])
        : "r"(a0), "r"(a1), "r"(a2), "r"(a3), "r"(b0), "r"(b1));
}

// 8-lane reduction (lanes differing in bits 0..2)
__device__ __forceinline__ float red8(float v) {
    v += __shfl_xor_sync(0xffffffffu, v, 1);
    v += __shfl_xor_sync(0xffffffffu, v, 2);
    v += __shfl_xor_sync(0xffffffffu, v, 4);
    return v;
}

// Reduce acc[16] with 16 shuffles; result for index (lane>>1)&15 on even lanes.
__device__ __forceinline__ float reduce16_scatter(float* acc, int lane) {
#pragma unroll
    for (int step = 16, n = 8; n >= 1; step >>= 1, n >>= 1) {
        bool hi = (lane & step) != 0;
#pragma unroll
        for (int i = 0; i < n; i++) {
            float send = hi ? acc[i] : acc[i + n];
            float recv = __shfl_xor_sync(0xffffffffu, send, step);
            acc[i] = (hi ? acc[i + n] : acc[i]) + recv;
        }
    }
    float v = acc[0];
    v += __shfl_xor_sync(0xffffffffu, v, 1);
    return v;
}

// ---------------------------------------------------------------------------
// Kernel 1 (fused): attention weights (tf32 MMA for xc; x2 folded into the
// staging; staging SOFTWARE-PIPELINED with double-buffered smem) + partial
// G = attn^T x (fp32, coalesced). Grid 256 x 256 thr, 128 tokens/block.
// ---------------------------------------------------------------------------
__global__ __launch_bounds__(256) void k_attn_g(const float* __restrict__ x,
                                                const float* __restrict__ centers,
                                                const float* __restrict__ log_scales) {
    __shared__ float    s_x   [2][128 * 36]; // tf32 x chunks, padded (36 KB)
    __shared__ unsigned s_bf  [2][512];      // B fragments (centers) (4 KB)
    __shared__ float    s_xc  [128 * 17];    // XC, padded (8.7 KB)
    __shared__ float    s_attn[128 * Sn];    // 8 KB
    __shared__ float    s_x2  [128];
    __shared__ float    s_part[256];
    __shared__ float    s_inv [Sn], s_bias[Sn];

    int tid  = threadIdx.x;
    int warp = tid >> 5, lane = tid & 31;
    int gid  = lane >> 2, tg = lane & 3;     // mma fragment coords
    long long tok0 = (long long)blockIdx.x * 128;
    const float* xb = x + tok0 * Dn;

    // ---- scale/bias precompute: c2 via 16 threads per splat ----
    {
        int sp = tid >> 4, p16 = tid & 15;
        const float4* cr = (const float4*)(centers + (long long)sp * Dn);
        float c2 = 0.f;
#pragma unroll
        for (int j = 0; j < 8; j++) {
            float4 v = cr[p16 + j * 16];
            c2 += v.x * v.x + v.y * v.y + v.z * v.z + v.w * v.w;
        }
        s_part[tid] = c2;
        __syncthreads();
        if (tid < Sn) {
            float c2t = 0.f;
#pragma unroll
            for (int k = 0; k < 16; k++) c2t += s_part[tid * 16 + k];
            float s = expf(log_scales[tid]);
            s = fminf(fmaxf(s, 0.1f), 2.0f);
            float inv = -0.5f / (s * s);
            s_inv[tid]  = inv;
            s_bias[tid] = inv * c2t;
        }
    }

    // ---- Phase 1: XC = x . centers^T via tf32 mma, pipelined staging ----
    float xcacc[2][4];
#pragma unroll
    for (int h = 0; h < 2; h++)
#pragma unroll
        for (int r = 0; r < 4; r++) xcacc[h][r] = 0.f;
    float x2p[4] = {0.f, 0.f, 0.f, 0.f};     // partial x2 for rows (tid>>3)+32i, col tid&7
    int tlw = warp * 16;                     // warp's m-tile token base

    int srow = (tid >> 3), sc4 = tid & 7;    // staging coords
    float4   pre[4];                          // prefetch registers (x)
    unsigned preb[2];                         // prefetch registers (centers frag)
    int pe[2];                                // bf indices

    // prefetch indices for bf: e = tid, tid+256
#pragma unroll
    for (int i = 0; i < 2; i++) pe[i] = tid + i * 256;

    // --- prologue: load chunk 0 ---
#pragma unroll
    for (int i = 0; i < 4; i++)
        pre[i] = ((const float4*)(xb + (long long)(srow + i * 32) * Dn))[sc4];
#pragma unroll
    for (int i = 0; i < 2; i++) {
        int e = pe[i];
        int kit8 = e >> 7, rem = e & 127;
        int h = rem >> 6, which = (rem >> 5) & 1, L = rem & 31;
        int k  = 0 * 32 + kit8 * 8 + (L & 3) + which * 4;
        int sp = h * 8 + (L >> 2);
        preb[i] = f2tf32(centers[(long long)sp * Dn + k]);
    }
    // store chunk 0 into buffer 0 (+x2 fold)
#pragma unroll
    for (int i = 0; i < 4; i++) {
        float4 v = pre[i];
        x2p[i] += v.x * v.x + v.y * v.y + v.z * v.z + v.w * v.w;
        float4 t;
        t.x = __uint_as_float(f2tf32(v.x));
        t.y = __uint_as_float(f2tf32(v.y));
        t.z = __uint_as_float(f2tf32(v.z));
        t.w = __uint_as_float(f2tf32(v.w));
        *(float4*)&s_x[0][(srow + i * 32) * 36 + sc4 * 4] = t;
    }
#pragma unroll
    for (int i = 0; i < 2; i++) s_bf[0][pe[i]] = preb[i];
    __syncthreads();

#pragma unroll 1
    for (int c = 0; c < 16; c++) {
        int cur = c & 1;
        // issue next chunk's loads BEFORE computing (latency overlap)
        if (c < 15) {
#pragma unroll
            for (int i = 0; i < 4; i++)
                pre[i] = ((const float4*)(xb + (long long)(srow + i * 32) * Dn))[(c + 1) * 8 + sc4];
#pragma unroll
            for (int i = 0; i < 2; i++) {
                int e = pe[i];
                int kit8 = e >> 7, rem = e & 127;
                int h = rem >> 6, which = (rem >> 5) & 1, L = rem & 31;
                int k  = (c + 1) * 32 + kit8 * 8 + (L & 3) + which * 4;
                int sp = h * 8 + (L >> 2);
                preb[i] = f2tf32(centers[(long long)sp * Dn + k]);
            }
        }
        // compute current chunk: 4 k-iterations of m16n8k8 per n-half
#pragma unroll
        for (int kit8 = 0; kit8 < 4; kit8++) {
            int kb = kit8 * 8;
            unsigned a0 = __float_as_uint(s_x[cur][(tlw + gid)     * 36 + kb + tg]);
            unsigned a1 = __float_as_uint(s_x[cur][(tlw + gid + 8) * 36 + kb + tg]);
            unsigned a2 = __float_as_uint(s_x[cur][(tlw + gid)     * 36 + kb + tg + 4]);
            unsigned a3 = __float_as_uint(s_x[cur][(tlw + gid + 8) * 36 + kb + tg + 4]);
#pragma unroll
            for (int h = 0; h < 2; h++) {
                unsigned b0 = s_bf[cur][kit8 * 128 + h * 64 + lane];
                unsigned b1 = s_bf[cur][kit8 * 128 + h * 64 + 32 + lane];
                mma_tf32(xcacc[h], a0, a1, a2, a3, b0, b1);
            }
        }
        // store prefetched chunk into the other buffer (+x2 fold)
        if (c < 15) {
            int nxt = cur ^ 1;
#pragma unroll
            for (int i = 0; i < 4; i++) {
                float4 v = pre[i];
                x2p[i] += v.x * v.x + v.y * v.y + v.z * v.z + v.w * v.w;
                float4 t;
                t.x = __uint_as_float(f2tf32(v.x));
                t.y = __uint_as_float(f2tf32(v.y));
                t.z = __uint_as_float(f2tf32(v.z));
                t.w = __uint_as_float(f2tf32(v.w));
                *(float4*)&s_x[nxt][(srow + i * 32) * 36 + sc4 * 4] = t;
            }
#pragma unroll
            for (int i = 0; i < 2; i++) s_bf[nxt][pe[i]] = preb[i];
        }
        __syncthreads();
    }

    // write XC fragments to padded smem
#pragma unroll
    for (int h = 0; h < 2; h++) {
        int col = h * 8 + tg * 2;
        s_xc[(tlw + gid)     * 17 + col]     = xcacc[h][0];
        s_xc[(tlw + gid)     * 17 + col + 1] = xcacc[h][1];
        s_xc[(tlw + gid + 8) * 17 + col]     = xcacc[h][2];
        s_xc[(tlw + gid + 8) * 17 + col + 1] = xcacc[h][3];
    }
    // finish x2: threads sharing a row differ in lane bits 0..2
#pragma unroll
    for (int i = 0; i < 4; i++) {
        float v = red8(x2p[i]);
        if ((tid & 7) == 0) s_x2[(tid >> 3) + i * 32] = v;
    }
    __syncthreads();

    // per-token softmax (threads 0..127)
    if (tid < 128) {
        float x2 = s_x2[tid];
        float l[Sn];
        float m = -1e30f;
#pragma unroll
        for (int s = 0; s < Sn; s++) {
            l[s] = s_inv[s] * (x2 - 2.f * s_xc[tid * 17 + s]) + s_bias[s];
            m = fmaxf(m, l[s]);
        }
        float sum = 0.f;
#pragma unroll
        for (int s = 0; s < Sn; s++) { l[s] = __expf(l[s] - m); sum += l[s]; }
        float r = 1.f / sum;
#pragma unroll
        for (int s = 0; s < Sn; s++) s_attn[tid * Sn + s] = l[s] * r;
    }
    __syncthreads();

    // coalesced copy s_attn -> g_attn
    for (int i = tid; i < 128 * Sn / 4; i += 256)
        ((float4*)(g_attn + tok0 * Sn))[i] = ((const float4*)s_attn)[i];

    // -------- Phase 2: G partial over this block's 128 tokens (fp32) --------
    float2 accG[Sn];
#pragma unroll
    for (int s = 0; s < Sn; s++) { accG[s].x = 0.f; accG[s].y = 0.f; }

#pragma unroll 8
    for (int t = 0; t < 128; t++) {
        float2 xv = ((const float2*)(xb + (long long)t * Dn))[tid];   // d = 2*tid, 2*tid+1
        const float4* ar = (const float4*)&s_attn[t * Sn];
#pragma unroll
        for (int q = 0; q < 4; q++) {
            float4 a = ar[q];
            accG[q*4+0].x += a.x * xv.x; accG[q*4+0].y += a.x * xv.y;
            accG[q*4+1].x += a.y * xv.x; accG[q*4+1].y += a.y * xv.y;
            accG[q*4+2].x += a.z * xv.x; accG[q*4+2].y += a.z * xv.y;
            accG[q*4+3].x += a.w * xv.x; accG[q*4+3].y += a.w * xv.y;
        }
    }

    int b = (int)(tok0 / Tn);
    int p = (int)((tok0 % Tn) / 128);
    float* gp = g_Gpart + ((long long)(b * PARTS + p) * Sn * Dn);
#pragma unroll
    for (int s = 0; s < Sn; s++)
        ((float2*)(gp + s * Dn))[tid] = accG[s];
}

// ---------------------------------------------------------------------------
// Kernel 2: reduce 64 partials -> G. 32768 outputs. Grid 128 x 256 thr.
// ---------------------------------------------------------------------------
__global__ void k_reduce() {
    int idx = blockIdx.x * blockDim.x + threadIdx.x;   // < Bn*Sn*Dn = 32768
    int b = idx >> 13;
    int r = idx & 8191;
    float sum = 0.f;
#pragma unroll
    for (int p = 0; p < PARTS; p++)
        sum += g_Gpart[(long long)(b * PARTS + p) * (Sn * Dn) + r];
    g_G[idx] = sum;
}

// ---------------------------------------------------------------------------
// Kernel 3: small GEMM out[row][k] = sum_d in[row][d] * W[k][d], rows = 64.
// Round-6 measured-best: grid (64,4) x 256 thr, 16 in-rows in smem,
// warp-per-column, plain float4 FMA, reduce-scatter finish.
// ---------------------------------------------------------------------------
__global__ __launch_bounds__(256) void k_small_gemm(const float* __restrict__ W, int stage) {
    const float* in  = (stage == 0) ? g_G : g_H;
    float*       out = (stage == 0) ? g_H : g_M;
    __shared__ float4 s_in[16 * 128];        // 32 KB

    int tid = threadIdx.x, warp = tid >> 5, lane = tid & 31;
    int kc = blockIdx.x;                     // 0..63 column chunk
    int b  = blockIdx.y;                     // 0..3 batch

    const float4* src = (const float4*)(in + (long long)b * 16 * Dn);
#pragma unroll
    for (int i = 0; i < 8; i++) s_in[tid + i * 256] = src[tid + i * 256];
    __syncthreads();

    int k = kc * 8 + warp;                   // output column, 0..511
    const float4* wr = (const float4*)(W + (long long)k * Dn);
    float4 w0 = wr[lane], w1 = wr[lane + 32], w2 = wr[lane + 64], w3 = wr[lane + 96];

    float acc[16];
#pragma unroll
    for (int r = 0; r < 16; r++) {
        float4 g0 = s_in[r * 128 + lane];
        float4 g1 = s_in[r * 128 + lane + 32];
        float4 g2 = s_in[r * 128 + lane + 64];
        float4 g3 = s_in[r * 128 + lane + 96];
        acc[r] = w0.x*g0.x + w0.y*g0.y + w0.z*g0.z + w0.w*g0.w
               + w1.x*g1.x + w1.y*g1.y + w1.z*g1.z + w1.w*g1.w
               + w2.x*g2.x + w2.y*g2.y + w2.z*g2.z + w2.w*g2.w
               + w3.x*g3.x + w3.y*g3.y + w3.z*g3.z + w3.w*g3.w;
    }
    float val = reduce16_scatter(acc, lane);
    int row = (lane >> 1) & 15;
    if ((lane & 1) == 0)
        out[(long long)(b * 16 + row) * Dn + k] = val;
}

// ---------------------------------------------------------------------------
// Kernel 4: y = attn . M via tf32 MMA. Grid 256 x 256 thr, 128 tokens/block.
// Warp owns a 16-token m-tile; loops 64 n-chunks of 8 dims; k = 16 splats
// (2 k-steps). attn (8 KB) + M (tf32, padded stride 520, 33 KB) in smem.
// ---------------------------------------------------------------------------
__global__ __launch_bounds__(256) void k_out(float* __restrict__ y) {
    __shared__ float s_a[128 * Sn];          // attn tile as tf32 (8 KB)
    __shared__ float s_m[16 * 520];          // M tile as tf32, padded (33.3 KB)
    int tid = threadIdx.x, warp = tid >> 5, lane = tid & 31;
    int gid = lane >> 2, tg = lane & 3;
    long long tok0 = (long long)blockIdx.x * 128;
    int b = (int)(tok0 / Tn);

    // stage attn as tf32 (coalesced float4)
#pragma unroll
    for (int i = 0; i < 2; i++) {
        float4 v = ((const float4*)(g_attn + tok0 * Sn))[tid + i * 256];
        float4 t;
        t.x = __uint_as_float(f2tf32(v.x));
        t.y = __uint_as_float(f2tf32(v.y));
        t.z = __uint_as_float(f2tf32(v.z));
        t.w = __uint_as_float(f2tf32(v.w));
        ((float4*)s_a)[tid + i * 256] = t;
    }
    // stage M as tf32, padded stride 520
    const float* Mb = g_M + (long long)b * Sn * Dn;
#pragma unroll
    for (int i = 0; i < 8; i++) {
        int e = tid + i * 256;               // 0..2047 = 16 rows x 128 float4
        int r = e >> 7, c4 = e & 127;
        float4 v = ((const float4*)(Mb + (long long)r * Dn))[c4];
        float4 t;
        t.x = __uint_as_float(f2tf32(v.x));
        t.y = __uint_as_float(f2tf32(v.y));
        t.z = __uint_as_float(f2tf32(v.z));
        t.w = __uint_as_float(f2tf32(v.w));
        *(float4*)&s_m[r * 520 + c4 * 4] = t;
    }
    __syncthreads();

    int tlw = warp * 16;                     // warp's 16-token m-tile
    // A fragments, both k-steps, loaded once (16 scalar LDS per warp)
    unsigned a00 = __float_as_uint(s_a[(tlw + gid)     * Sn + tg]);
    unsigned a01 = __float_as_uint(s_a[(tlw + gid + 8) * Sn + tg]);
    unsigned a02 = __float_as_uint(s_a[(tlw + gid)     * Sn + tg + 4]);
    unsigned a03 = __float_as_uint(s_a[(tlw + gid + 8) * Sn + tg + 4]);
    unsigned a10 = __float_as_uint(s_a[(tlw + gid)     * Sn + tg + 8]);
    unsigned a11 = __float_as_uint(s_a[(tlw + gid + 8) * Sn + tg + 8]);
    unsigned a12 = __float_as_uint(s_a[(tlw + gid)     * Sn + tg + 12]);
    unsigned a13 = __float_as_uint(s_a[(tlw + gid + 8) * Sn + tg + 12]);

    float* y0 = y + (tok0 + tlw + gid)     * Dn + 2 * tg;
    float* y1 = y + (tok0 + tlw + gid + 8) * Dn + 2 * tg;

#pragma unroll 4
    for (int d0 = 0; d0 < Dn; d0 += 8) {
        float c[4] = {0.f, 0.f, 0.f, 0.f};
        unsigned b00 = __float_as_uint(s_m[ tg      * 520 + d0 + gid]);
        unsigned b01 = __float_as_uint(s_m[(tg + 4) * 520 + d0 + gid]);
        mma_tf32(c, a00, a01, a02, a03, b00, b01);
        unsigned b10 = __float_as_uint(s_m[(tg + 8)  * 520 + d0 + gid]);
        unsigned b11 = __float_as_uint(s_m[(tg + 12) * 520 + d0 + gid]);
        mma_tf32(c, a10, a11, a12, a13, b10, b11);
        *(float2*)(y0 + d0) = make_float2(c[0], c[1]);
        *(float2*)(y1 + d0) = make_float2(c[2], c[3]);
    }
}

// ---------------------------------------------------------------------------
extern "C" void kernel_launch(void* const* d_in, const int* in_sizes, int n_in,
                              void* d_out, int out_size) {
    (void)in_sizes; (void)n_in; (void)out_size;
    const float* x          = (const float*)d_in[0];   // [B,T,D]
    const float* centers    = (const float*)d_in[1];   // [S,D]
    const float* log_scales = (const float*)d_in[2];   // [S]
    const float* Wv         = (const float*)d_in[3];   // [D,D]
    const float* Wo         = (const float*)d_in[4];   // [D,D]
    float* y = (float*)d_out;                          // [B,T,D] fp32

    k_attn_g<<<256, 256>>>(x, centers, log_scales);
    k_reduce<<<128, 256>>>();
    k_small_gemm<<<dim3(64, 4), 256>>>(Wv, 0);
    k_small_gemm<<<dim3(64, 4), 256>>>(Wo, 1);
    k_out<<<256, 256>>>(y);
}

// round 14
// speedup vs baseline: 1.5997x; 1.0893x over previous
#include <cuda_runtime.h>
#include <math.h>

#define Bn 4
#define Tn 8192
#define Dn 512
#define Sn 16
#define PARTS 64   // 256 blocks / 4 batches in the fused attn+G pass

// Scratch (static device globals — allocation-free per harness rules)
__device__ float g_attn [Bn*Tn*Sn];          // 2 MB
__device__ float g_Gpart[Bn*PARTS*Sn*Dn];    // 8 MB
__device__ float g_G    [Bn*Sn*Dn];
__device__ float g_Wf   [Dn*Dn];             // 1 MB: Wf = Wo . Wv
__device__ float g_M    [Bn*Sn*Dn];

__device__ __forceinline__ unsigned f2tf32(float f) {
    unsigned r; asm("cvt.rna.tf32.f32 %0, %1;" : "=r"(r) : "f"(f));
    return r;
}

__device__ __forceinline__ float4 tf32x4(float4 v) {
    float4 t;
    t.x = __uint_as_float(f2tf32(v.x));
    t.y = __uint_as_float(f2tf32(v.y));
    t.z = __uint_as_float(f2tf32(v.z));
    t.w = __uint_as_float(f2tf32(v.w));
    return t;
}

__device__ __forceinline__ void mma_tf32(float c[4],
    unsigned a0, unsigned a1, unsigned a2, unsigned a3,
    unsigned b0, unsigned b1) {
    asm("mma.sync.aligned.m16n8k8.row.col.f32.tf32.tf32.f32 "
        "{%0,%1,%2,%3}, {%4,%5,%6,%7}, {%8,%9}, {%0,%1,%2,%3};"
        : "+f"(c[0]), "+f"(c[1]), "+f"(c[2]), "+f"(c[3])
        : "r"(a0), "r"(a1), "r"(a2), "r"(a3), "r"(b0), "r"(b1));
}

// 8-lane reduction (lanes differing in bits 0..2)
__device__ __forceinline__ float red8(float v) {
    v += __shfl_xor_sync(0xffffffffu, v, 1);
    v += __shfl_xor_sync(0xffffffffu, v, 2);
    v += __shfl_xor_sync(0xffffffffu, v, 4);
    return v;
}

// Reduce acc[16] with 16 shuffles; result for index (lane>>1)&15 on even lanes.
__device__ __forceinline__ float reduce16_scatter(float* acc, int lane) {
#pragma unroll
    for (int step = 16, n = 8; n >= 1; step >>= 1, n >>= 1) {
        bool hi = (lane & step) != 0;
#pragma unroll
        for (int i = 0; i < n; i++) {
            float send = hi ? acc[i] : acc[i + n];
            float recv = __shfl_xor_sync(0xffffffffu, send, step);
            acc[i] = (hi ? acc[i + n] : acc[i]) + recv;
        }
    }
    float v = acc[0];
    v += __shfl_xor_sync(0xffffffffu, v, 1);
    return v;
}

// ---------------------------------------------------------------------------
// Kernel 1 (fused): blocks 0..255: attention weights (tf32 MMA, pipelined
// staging, x2 folded) + partial G = attn^T x (fp32). Blocks 256..287: Wf =
// Wo . Wv via tf32 MMA (128x64 tile each), overlapped — 288 blocks = 1 wave.
// ---------------------------------------------------------------------------
__global__ __launch_bounds__(256, 2) void k_attn_g(const float* __restrict__ x,
                                                   const float* __restrict__ centers,
                                                   const float* __restrict__ log_scales,
                                                   const float* __restrict__ Wv,
                                                   const float* __restrict__ Wo) {
    __shared__ float    s_x   [2][128 * 36]; // tf32 x chunks, padded (36 KB)
    __shared__ unsigned s_bf  [2][512];      // B fragments (centers) (4 KB)
    __shared__ float    s_xc  [128 * 17];    // XC, padded (8.7 KB)
    __shared__ float    s_attn[128 * Sn];    // 8 KB
    __shared__ float    s_x2  [128];
    __shared__ float    s_part[256];
    __shared__ float    s_inv [Sn], s_bias[Sn];

    int tid  = threadIdx.x;
    int warp = tid >> 5, lane = tid & 31;
    int gid  = lane >> 2, tg = lane & 3;     // mma fragment coords
    int tlw  = warp * 16;                    // warp's m-tile base
    int srow = (tid >> 3), sc4 = tid & 7;    // staging coords

    // =============== Wf blocks: Wf = Wo . Wv (tf32 MMA) ===============
    if (blockIdx.x >= 256) {
        int wfb  = blockIdx.x - 256;         // 0..31
        int row0 = (wfb & 3) * 128;          // Wo row stripe
        int col0 = (wfb >> 2) * 64;          // Wv col stripe
        float* s_wo = s_x[0];                // 128 x 36 (reuse)
        float* s_wv = s_xc;                  // 32 x 68 = 2176 floats (reuse)

        float cw[8][4];
#pragma unroll
        for (int n = 0; n < 8; n++)
#pragma unroll
            for (int r = 0; r < 4; r++) cw[n][r] = 0.f;

#pragma unroll 1
        for (int c = 0; c < 16; c++) {
            // stage Wo chunk (rows row0..row0+127, cols c*32..+31), tf32, stride 36
#pragma unroll
            for (int i = 0; i < 4; i++) {
                int row = srow + i * 32;
                float4 v = ((const float4*)(Wo + (long long)(row0 + row) * Dn))[c * 8 + sc4];
                *(float4*)&s_wo[row * 36 + sc4 * 4] = tf32x4(v);
            }
            // stage Wv chunk (rows c*32..+31, cols col0..col0+63), tf32, stride 68
#pragma unroll
            for (int i = 0; i < 2; i++) {
                int idx = tid + i * 256;     // 0..511 = 32 rows x 16 float4
                int e = idx >> 4, j4 = idx & 15;
                float4 v = ((const float4*)(Wv + (long long)(c * 32 + e) * Dn + col0))[j4];
                *(float4*)&s_wv[e * 68 + j4 * 4] = tf32x4(v);
            }
            __syncthreads();
#pragma unroll
            for (int kit8 = 0; kit8 < 4; kit8++) {
                int kb = kit8 * 8;
                unsigned a0 = __float_as_uint(s_wo[(tlw + gid)     * 36 + kb + tg]);
                unsigned a1 = __float_as_uint(s_wo[(tlw + gid + 8) * 36 + kb + tg]);
                unsigned a2 = __float_as_uint(s_wo[(tlw + gid)     * 36 + kb + tg + 4]);
                unsigned a3 = __float_as_uint(s_wo[(tlw + gid + 8) * 36 + kb + tg + 4]);
#pragma unroll
                for (int nch = 0; nch < 8; nch++) {
                    unsigned b0 = __float_as_uint(s_wv[(kb + tg)     * 68 + nch * 8 + gid]);
                    unsigned b1 = __float_as_uint(s_wv[(kb + tg + 4) * 68 + nch * 8 + gid]);
                    mma_tf32(cw[nch], a0, a1, a2, a3, b0, b1);
                }
            }
            __syncthreads();
        }
        // store 128x64 tile
#pragma unroll
        for (int nch = 0; nch < 8; nch++) {
            int r0 = row0 + tlw + gid;
            int cc = col0 + nch * 8 + tg * 2;
            g_Wf[(long long)r0       * Dn + cc]     = cw[nch][0];
            g_Wf[(long long)r0       * Dn + cc + 1] = cw[nch][1];
            g_Wf[(long long)(r0 + 8) * Dn + cc]     = cw[nch][2];
            g_Wf[(long long)(r0 + 8) * Dn + cc + 1] = cw[nch][3];
        }
        return;
    }

    // =============== attention blocks (round-13 measured-best) ===============
    long long tok0 = (long long)blockIdx.x * 128;
    const float* xb = x + tok0 * Dn;

    // ---- scale/bias precompute: c2 via 16 threads per splat ----
    {
        int sp = tid >> 4, p16 = tid & 15;
        const float4* cr = (const float4*)(centers + (long long)sp * Dn);
        float c2 = 0.f;
#pragma unroll
        for (int j = 0; j < 8; j++) {
            float4 v = cr[p16 + j * 16];
            c2 += v.x * v.x + v.y * v.y + v.z * v.z + v.w * v.w;
        }
        s_part[tid] = c2;
        __syncthreads();
        if (tid < Sn) {
            float c2t = 0.f;
#pragma unroll
            for (int k = 0; k < 16; k++) c2t += s_part[tid * 16 + k];
            float s = expf(log_scales[tid]);
            s = fminf(fmaxf(s, 0.1f), 2.0f);
            float inv = -0.5f / (s * s);
            s_inv[tid]  = inv;
            s_bias[tid] = inv * c2t;
        }
    }

    // ---- Phase 1: XC = x . centers^T via tf32 mma, pipelined staging ----
    float xcacc[2][4];
#pragma unroll
    for (int h = 0; h < 2; h++)
#pragma unroll
        for (int r = 0; r < 4; r++) xcacc[h][r] = 0.f;
    float x2p[4] = {0.f, 0.f, 0.f, 0.f};     // partial x2 for rows (tid>>3)+32i, col tid&7

    float4   pre[4];                          // prefetch registers (x)
    unsigned preb[2];                         // prefetch registers (centers frag)
    int pe[2];
#pragma unroll
    for (int i = 0; i < 2; i++) pe[i] = tid + i * 256;

    // --- prologue: load chunk 0 ---
#pragma unroll
    for (int i = 0; i < 4; i++)
        pre[i] = ((const float4*)(xb + (long long)(srow + i * 32) * Dn))[sc4];
#pragma unroll
    for (int i = 0; i < 2; i++) {
        int e = pe[i];
        int kit8 = e >> 7, rem = e & 127;
        int h = rem >> 6, which = (rem >> 5) & 1, L = rem & 31;
        int k  = kit8 * 8 + (L & 3) + which * 4;
        int sp = h * 8 + (L >> 2);
        preb[i] = f2tf32(centers[(long long)sp * Dn + k]);
    }
#pragma unroll
    for (int i = 0; i < 4; i++) {
        float4 v = pre[i];
        x2p[i] += v.x * v.x + v.y * v.y + v.z * v.z + v.w * v.w;
        *(float4*)&s_x[0][(srow + i * 32) * 36 + sc4 * 4] = tf32x4(v);
    }
#pragma unroll
    for (int i = 0; i < 2; i++) s_bf[0][pe[i]] = preb[i];
    __syncthreads();

#pragma unroll 1
    for (int c = 0; c < 16; c++) {
        int cur = c & 1;
        if (c < 15) {
#pragma unroll
            for (int i = 0; i < 4; i++)
                pre[i] = ((const float4*)(xb + (long long)(srow + i * 32) * Dn))[(c + 1) * 8 + sc4];
#pragma unroll
            for (int i = 0; i < 2; i++) {
                int e = pe[i];
                int kit8 = e >> 7, rem = e & 127;
                int h = rem >> 6, which = (rem >> 5) & 1, L = rem & 31;
                int k  = (c + 1) * 32 + kit8 * 8 + (L & 3) + which * 4;
                int sp = h * 8 + (L >> 2);
                preb[i] = f2tf32(centers[(long long)sp * Dn + k]);
            }
        }
#pragma unroll
        for (int kit8 = 0; kit8 < 4; kit8++) {
            int kb = kit8 * 8;
            unsigned a0 = __float_as_uint(s_x[cur][(tlw + gid)     * 36 + kb + tg]);
            unsigned a1 = __float_as_uint(s_x[cur][(tlw + gid + 8) * 36 + kb + tg]);
            unsigned a2 = __float_as_uint(s_x[cur][(tlw + gid)     * 36 + kb + tg + 4]);
            unsigned a3 = __float_as_uint(s_x[cur][(tlw + gid + 8) * 36 + kb + tg + 4]);
#pragma unroll
            for (int h = 0; h < 2; h++) {
                unsigned b0 = s_bf[cur][kit8 * 128 + h * 64 + lane];
                unsigned b1 = s_bf[cur][kit8 * 128 + h * 64 + 32 + lane];
                mma_tf32(xcacc[h], a0, a1, a2, a3, b0, b1);
            }
        }
        if (c < 15) {
            int nxt = cur ^ 1;
#pragma unroll
            for (int i = 0; i < 4; i++) {
                float4 v = pre[i];
                x2p[i] += v.x * v.x + v.y * v.y + v.z * v.z + v.w * v.w;
                *(float4*)&s_x[nxt][(srow + i * 32) * 36 + sc4 * 4] = tf32x4(v);
            }
#pragma unroll
            for (int i = 0; i < 2; i++) s_bf[nxt][pe[i]] = preb[i];
        }
        __syncthreads();
    }

    // write XC fragments to padded smem
#pragma unroll
    for (int h = 0; h < 2; h++) {
        int col = h * 8 + tg * 2;
        s_xc[(tlw + gid)     * 17 + col]     = xcacc[h][0];
        s_xc[(tlw + gid)     * 17 + col + 1] = xcacc[h][1];
        s_xc[(tlw + gid + 8) * 17 + col]     = xcacc[h][2];
        s_xc[(tlw + gid + 8) * 17 + col + 1] = xcacc[h][3];
    }
    // finish x2
#pragma unroll
    for (int i = 0; i < 4; i++) {
        float v = red8(x2p[i]);
        if ((tid & 7) == 0) s_x2[(tid >> 3) + i * 32] = v;
    }
    __syncthreads();

    // per-token softmax (threads 0..127)
    if (tid < 128) {
        float x2 = s_x2[tid];
        float l[Sn];
        float m = -1e30f;
#pragma unroll
        for (int s = 0; s < Sn; s++) {
            l[s] = s_inv[s] * (x2 - 2.f * s_xc[tid * 17 + s]) + s_bias[s];
            m = fmaxf(m, l[s]);
        }
        float sum = 0.f;
#pragma unroll
        for (int s = 0; s < Sn; s++) { l[s] = __expf(l[s] - m); sum += l[s]; }
        float r = 1.f / sum;
#pragma unroll
        for (int s = 0; s < Sn; s++) s_attn[tid * Sn + s] = l[s] * r;
    }
    __syncthreads();

    // coalesced copy s_attn -> g_attn
    for (int i = tid; i < 128 * Sn / 4; i += 256)
        ((float4*)(g_attn + tok0 * Sn))[i] = ((const float4*)s_attn)[i];

    // -------- Phase 2: G partial over this block's 128 tokens (fp32) --------
    float2 accG[Sn];
#pragma unroll
    for (int s = 0; s < Sn; s++) { accG[s].x = 0.f; accG[s].y = 0.f; }

#pragma unroll 8
    for (int t = 0; t < 128; t++) {
        float2 xv = ((const float2*)(xb + (long long)t * Dn))[tid];   // d = 2*tid, 2*tid+1
        const float4* ar = (const float4*)&s_attn[t * Sn];
#pragma unroll
        for (int q = 0; q < 4; q++) {
            float4 a = ar[q];
            accG[q*4+0].x += a.x * xv.x; accG[q*4+0].y += a.x * xv.y;
            accG[q*4+1].x += a.y * xv.x; accG[q*4+1].y += a.y * xv.y;
            accG[q*4+2].x += a.z * xv.x; accG[q*4+2].y += a.z * xv.y;
            accG[q*4+3].x += a.w * xv.x; accG[q*4+3].y += a.w * xv.y;
        }
    }

    int b = (int)(tok0 / Tn);
    int p = (int)((tok0 % Tn) / 128);
    float* gp = g_Gpart + ((long long)(b * PARTS + p) * Sn * Dn);
#pragma unroll
    for (int s = 0; s < Sn; s++)
        ((float2*)(gp + s * Dn))[tid] = accG[s];
}

// ---------------------------------------------------------------------------
// Kernel 2: reduce 64 partials -> G. 32768 outputs. Grid 128 x 256 thr.
// ---------------------------------------------------------------------------
__global__ void k_reduce() {
    int idx = blockIdx.x * blockDim.x + threadIdx.x;   // < Bn*Sn*Dn = 32768
    int b = idx >> 13;
    int r = idx & 8191;
    float sum = 0.f;
#pragma unroll
    for (int p = 0; p < PARTS; p++)
        sum += g_Gpart[(long long)(b * PARTS + p) * (Sn * Dn) + r];
    g_G[idx] = sum;
}

// ---------------------------------------------------------------------------
// Kernel 3: single small GEMM M[row][k] = sum_d G[row][d] * Wf[k][d], rows=64.
// Round-6 measured-best body: grid (64,4) x 256 thr, 16 in-rows in smem,
// warp-per-column, plain float4 FMA, reduce-scatter finish.
// ---------------------------------------------------------------------------
__global__ __launch_bounds__(256) void k_small_gemm() {
    __shared__ float4 s_in[16 * 128];        // 32 KB

    int tid = threadIdx.x, warp = tid >> 5, lane = tid & 31;
    int kc = blockIdx.x;                     // 0..63 column chunk
    int b  = blockIdx.y;                     // 0..3 batch

    const float4* src = (const float4*)(g_G + (long long)b * 16 * Dn);
#pragma unroll
    for (int i = 0; i < 8; i++) s_in[tid + i * 256] = src[tid + i * 256];
    __syncthreads();

    int k = kc * 8 + warp;                   // output column, 0..511
    const float4* wr = (const float4*)(g_Wf + (long long)k * Dn);
    float4 w0 = wr[lane], w1 = wr[lane + 32], w2 = wr[lane + 64], w3 = wr[lane + 96];

    float acc[16];
#pragma unroll
    for (int r = 0; r < 16; r++) {
        float4 g0 = s_in[r * 128 + lane];
        float4 g1 = s_in[r * 128 + lane + 32];
        float4 g2 = s_in[r * 128 + lane + 64];
        float4 g3 = s_in[r * 128 + lane + 96];
        acc[r] = w0.x*g0.x + w0.y*g0.y + w0.z*g0.z + w0.w*g0.w
               + w1.x*g1.x + w1.y*g1.y + w1.z*g1.z + w1.w*g1.w
               + w2.x*g2.x + w2.y*g2.y + w2.z*g2.z + w2.w*g2.w
               + w3.x*g3.x + w3.y*g3.y + w3.z*g3.z + w3.w*g3.w;
    }
    float val = reduce16_scatter(acc, lane);
    int row = (lane >> 1) & 15;
    if ((lane & 1) == 0)
        g_M[(long long)(b * 16 + row) * Dn + k] = val;
}

// ---------------------------------------------------------------------------
// Kernel 4: y = attn . M via tf32 MMA. Grid 256 x 256 thr, 128 tokens/block.
// ---------------------------------------------------------------------------
__global__ __launch_bounds__(256) void k_out(float* __restrict__ y) {
    __shared__ float s_a[128 * Sn];          // attn tile as tf32 (8 KB)
    __shared__ float s_m[16 * 520];          // M tile as tf32, padded (33.3 KB)
    int tid = threadIdx.x, warp = tid >> 5, lane = tid & 31;
    int gid = lane >> 2, tg = lane & 3;
    long long tok0 = (long long)blockIdx.x * 128;
    int b = (int)(tok0 / Tn);

    // stage attn as tf32 (coalesced float4)
#pragma unroll
    for (int i = 0; i < 2; i++) {
        float4 v = ((const float4*)(g_attn + tok0 * Sn))[tid + i * 256];
        ((float4*)s_a)[tid + i * 256] = tf32x4(v);
    }
    // stage M as tf32, padded stride 520
    const float* Mb = g_M + (long long)b * Sn * Dn;
#pragma unroll
    for (int i = 0; i < 8; i++) {
        int e = tid + i * 256;               // 0..2047 = 16 rows x 128 float4
        int r = e >> 7, c4 = e & 127;
        float4 v = ((const float4*)(Mb + (long long)r * Dn))[c4];
        *(float4*)&s_m[r * 520 + c4 * 4] = tf32x4(v);
    }
    __syncthreads();

    int tlw = warp * 16;                     // warp's 16-token m-tile
    unsigned a00 = __float_as_uint(s_a[(tlw + gid)     * Sn + tg]);
    unsigned a01 = __float_as_uint(s_a[(tlw + gid + 8) * Sn + tg]);
    unsigned a02 = __float_as_uint(s_a[(tlw + gid)     * Sn + tg + 4]);
    unsigned a03 = __float_as_uint(s_a[(tlw + gid + 8) * Sn + tg + 4]);
    unsigned a10 = __float_as_uint(s_a[(tlw + gid)     * Sn + tg + 8]);
    unsigned a11 = __float_as_uint(s_a[(tlw + gid + 8) * Sn + tg + 8]);
    unsigned a12 = __float_as_uint(s_a[(tlw + gid)     * Sn + tg + 12]);
    unsigned a13 = __float_as_uint(s_a[(tlw + gid + 8) * Sn + tg + 12]);

    float* y0 = y + (tok0 + tlw + gid)     * Dn + 2 * tg;
    float* y1 = y + (tok0 + tlw + gid + 8) * Dn + 2 * tg;

#pragma unroll 4
    for (int d0 = 0; d0 < Dn; d0 += 8) {
        float c[4] = {0.f, 0.f, 0.f, 0.f};
        unsigned b00 = __float_as_uint(s_m[ tg      * 520 + d0 + gid]);
        unsigned b01 = __float_as_uint(s_m[(tg + 4) * 520 + d0 + gid]);
        mma_tf32(c, a00, a01, a02, a03, b00, b01);
        unsigned b10 = __float_as_uint(s_m[(tg + 8)  * 520 + d0 + gid]);
        unsigned b11 = __float_as_uint(s_m[(tg + 12) * 520 + d0 + gid]);
        mma_tf32(c, a10, a11, a12, a13, b10, b11);
        *(float2*)(y0 + d0) = make_float2(c[0], c[1]);
        *(float2*)(y1 + d0) = make_float2(c[2], c[3]);
    }
}

// ---------------------------------------------------------------------------
extern "C" void kernel_launch(void* const* d_in, const int* in_sizes, int n_in,
                              void* d_out, int out_size) {
    (void)in_sizes; (void)n_in; (void)out_size;
    const float* x          = (const float*)d_in[0];   // [B,T,D]
    const float* centers    = (const float*)d_in[1];   // [S,D]
    const float* log_scales = (const float*)d_in[2];   // [S]
    const float* Wv         = (const float*)d_in[3];   // [D,D]
    const float* Wo         = (const float*)d_in[4];   // [D,D]
    float* y = (float*)d_out;                          // [B,T,D] fp32

    k_attn_g<<<288, 256>>>(x, centers, log_scales, Wv, Wo);
    k_reduce<<<128, 256>>>();
    k_small_gemm<<<dim3(64, 4), 256>>>();
    k_out<<<256, 256>>>(y);
}